// round 8
// baseline (speedup 1.0000x reference)
#include <cuda_runtime.h>
#include <cuda_bf16.h>
#include <stdint.h>
#include <math.h>

#define BB 8
#define NN 2048
#define DIN 512
#define DOUT 256
#define NBUCK 20
#define ROWS (BB*NN)   // 16384

// ---------------- scratch (static __device__, no allocations) ----------------
__device__ __nv_bfloat16 g_qb[ROWS*DOUT];   // 8 MB
__device__ __nv_bfloat16 g_kb[ROWS*DOUT];   // 8 MB
__device__ float g_s[ROWS];
__device__ float g_gate3[NBUCK];            // sigmoid(rw*emb) * log2(e) / 16
__device__ float g_wvs[DIN];
__device__ float g_bvs;

// ======================= helpers =======================
__device__ __forceinline__ uint32_t s2u(const void* p) {
    return (uint32_t)__cvta_generic_to_shared(p);
}

// swizzled smem byte offset for a 128row x 256col bf16 tile (512B rows, 32 16B chunks)
__device__ __forceinline__ uint32_t sw(uint32_t row, uint32_t chunk) {
    return row * 512u + ((chunk ^ (row & 7u)) << 4);
}

#define LDSM4(r0,r1,r2,r3,a)                                                     \
    asm volatile("ldmatrix.sync.aligned.m8n8.x4.shared.b16 {%0,%1,%2,%3}, [%4];" \
        : "=r"(r0), "=r"(r1), "=r"(r2), "=r"(r3) : "r"(a))

__device__ __forceinline__ void mma16816(float* c, uint32_t a0, uint32_t a1,
                                         uint32_t a2, uint32_t a3,
                                         uint32_t b0, uint32_t b1) {
    asm volatile("mma.sync.aligned.m16n8k16.row.col.f32.bf16.bf16.f32 "
        "{%0,%1,%2,%3}, {%4,%5,%6,%7}, {%8,%9}, {%0,%1,%2,%3};"
        : "+f"(c[0]), "+f"(c[1]), "+f"(c[2]), "+f"(c[3])
        : "r"(a0), "r"(a1), "r"(a2), "r"(a3), "r"(b0), "r"(b1));
}

#define CP16(dst, src) asm volatile("cp.async.cg.shared.global [%0], [%1], 16;" :: "r"(dst), "l"(src) : "memory")
#define CP_COMMIT()    asm volatile("cp.async.commit_group;" ::: "memory")
#define CP_WAIT0()     asm volatile("cp.async.wait_group 0;" ::: "memory")

// fast 2^y, rel err ~2e-6, pure fma pipe (no MUFU)
__device__ __forceinline__ float exp2_fast(float y) {
    float z = y + 12582912.0f;
    float f = y - (z - 12582912.0f);
    uint32_t n = (uint32_t)__float_as_int(z);
    float p = 1.3333558146e-3f;
    p = fmaf(p, f, 9.6181291e-3f);
    p = fmaf(p, f, 5.5504109e-2f);
    p = fmaf(p, f, 2.4022652e-1f);
    p = fmaf(p, f, 6.9314718e-1f);
    p = fmaf(p, f, 1.0f);
    return __uint_as_float((n << 23) + 0x3f800000u) * p;
}

// ======================= prep: gate LUT + collapsed V path =======================
__global__ void prep_kernel(const float* __restrict__ Wv, const float* __restrict__ bv,
                            const float* __restrict__ Ws, const float* __restrict__ remb,
                            const float* __restrict__ rw) {
    int t = threadIdx.x;
    if (t < NBUCK) {
        float zv = rw[0] * remb[t];
        float sg = 1.f / (1.f + expf(-zv));
        g_gate3[t] = sg * (1.44269504088896f / 16.0f);  // fold log2e / sqrt(DOUT)
    }
    if (t < DIN) {
        float acc = 0.f;
        for (int o = 0; o < DOUT; o++) acc += Wv[o*DIN + t] * Ws[o];
        g_wvs[t] = acc;
    }
    if (t == 0) {
        float acc = 0.f;
        for (int o = 0; o < DOUT; o++) acc += bv[o] * Ws[o];
        g_bvs = acc;
    }
}

// ======================= s[b,m] = x . wvs + bvs =======================
__global__ void s_kernel(const float* __restrict__ x) {
    int row  = blockIdx.x * 8 + (threadIdx.x >> 5);
    int lane = threadIdx.x & 31;
    const float4* xr = (const float4*)(x + (size_t)row * DIN);
    const float4* wv = (const float4*)g_wvs;
    float acc = 0.f;
    #pragma unroll
    for (int i = 0; i < 4; i++) {
        float4 a = xr[lane + i * 32];
        float4 b = wv[lane + i * 32];
        acc += a.x*b.x + a.y*b.y + a.z*b.z + a.w*b.w;
    }
    #pragma unroll
    for (int s = 16; s; s >>= 1) acc += __shfl_xor_sync(0xffffffffu, acc, s);
    if (lane == 0) g_s[row] = acc + g_bvs;
}

// ======================= QK projection: mma.sync bf16, 512 threads =======================
// C[128 rows, 128 feats] = x[128,512] . W[128,512]^T, two smem K-halves of 256.
// 16 warps: 8 row-groups x 2 col-groups; each warp 16 rows x 64 cols.
#define QK_SMEM (1024 + 65536 + 65536)

__global__ __launch_bounds__(512, 1) void qk_mma(const float* __restrict__ x,
        const float* __restrict__ Wq, const float* __restrict__ bq,
        const float* __restrict__ Wk, const float* __restrict__ bk) {
    extern __shared__ char dsm[];
    uint32_t base0 = s2u(dsm);
    uint32_t A0 = (base0 + 1023u) & ~1023u;
    char* P = dsm + (A0 - base0);

    const int t = threadIdx.x, w = t >> 5, lane = t & 31;
    const int wr = w >> 1, wc = w & 1;
    const int row0 = blockIdx.x * 128;
    int yc = blockIdx.y;
    const float* W; const float* bias; __nv_bfloat16* outp;
    if (yc < 2) { W = Wq; bias = bq; outp = g_qb; }
    else        { W = Wk; bias = bk; outp = g_kb; yc -= 2; }
    const int col0 = yc * 128;

    const uint32_t SA = A0;
    const uint32_t SB = A0 + 65536;
    char* pA = P;
    char* pB = P + 65536;

    const int w16 = wr * 16;
    float acc[8][4];
    #pragma unroll
    for (int j = 0; j < 8; j++) { acc[j][0]=0.f; acc[j][1]=0.f; acc[j][2]=0.f; acc[j][3]=0.f; }

    const uint32_t arow = (uint32_t)(w16 + ((lane >> 3) & 1) * 8 + (lane & 7));
    const uint32_t ac   = (uint32_t)((lane >> 4) & 1);
    const uint32_t brlo = (uint32_t)(wc * 64 + ((lane >> 4) & 1) * 8 + (lane & 7));
    const uint32_t bc   = (uint32_t)((lane >> 3) & 1);

    for (int h = 0; h < 2; h++) {
        // fill A (x) and B (W) bf16 swizzled tiles for this K-half
        #pragma unroll
        for (int it = 0; it < 8; it++) {
            int idx = t + it * 512;
            int r = idx >> 5, c = idx & 31;
            const float* ps = x + (size_t)(row0 + r) * DIN + h * 256 + c * 8;
            float4 f0 = *(const float4*)ps;
            float4 f1 = *(const float4*)(ps + 4);
            __nv_bfloat162 h0 = __floats2bfloat162_rn(f0.x, f0.y);
            __nv_bfloat162 h1 = __floats2bfloat162_rn(f0.z, f0.w);
            __nv_bfloat162 h2 = __floats2bfloat162_rn(f1.x, f1.y);
            __nv_bfloat162 h3 = __floats2bfloat162_rn(f1.z, f1.w);
            uint4 u;
            u.x = *(uint32_t*)&h0; u.y = *(uint32_t*)&h1;
            u.z = *(uint32_t*)&h2; u.w = *(uint32_t*)&h3;
            *(uint4*)(pA + sw(r, c)) = u;

            const float* pw = W + (size_t)(col0 + r) * DIN + h * 256 + c * 8;
            f0 = *(const float4*)pw;
            f1 = *(const float4*)(pw + 4);
            h0 = __floats2bfloat162_rn(f0.x, f0.y);
            h1 = __floats2bfloat162_rn(f0.z, f0.w);
            h2 = __floats2bfloat162_rn(f1.x, f1.y);
            h3 = __floats2bfloat162_rn(f1.z, f1.w);
            u.x = *(uint32_t*)&h0; u.y = *(uint32_t*)&h1;
            u.z = *(uint32_t*)&h2; u.w = *(uint32_t*)&h3;
            *(uint4*)(pB + sw(r, c)) = u;
        }
        __syncthreads();

        #pragma unroll
        for (int ks = 0; ks < 16; ks++) {
            uint32_t a0, a1, a2, a3;
            LDSM4(a0, a1, a2, a3, SA + sw(arow, (uint32_t)(ks * 2) + ac));
            #pragma unroll
            for (int nb = 0; nb < 4; nb++) {
                uint32_t b0, b1, b2, b3;
                LDSM4(b0, b1, b2, b3, SB + sw((uint32_t)(nb * 16) + brlo, (uint32_t)(ks * 2) + bc));
                mma16816(acc[nb * 2],     a0, a1, a2, a3, b0, b1);
                mma16816(acc[nb * 2 + 1], a0, a1, a2, a3, b2, b3);
            }
        }
        __syncthreads();
    }

    // epilogue: bias add, bf16 store
    const int r0 = row0 + w16 + (lane >> 2);
    #pragma unroll
    for (int j = 0; j < 8; j++) {
        int col = col0 + wc * 64 + j * 8 + (lane & 3) * 2;
        float b0 = __ldg(bias + col), b1 = __ldg(bias + col + 1);
        __nv_bfloat162 lo = __floats2bfloat162_rn(acc[j][0] + b0, acc[j][1] + b1);
        __nv_bfloat162 hi = __floats2bfloat162_rn(acc[j][2] + b0, acc[j][3] + b1);
        *(uint32_t*)(outp + (size_t)r0 * DOUT + col)       = *(uint32_t*)&lo;
        *(uint32_t*)(outp + (size_t)(r0 + 8) * DOUT + col) = *(uint32_t*)&hi;
    }
}

// ======================= fused attention: mma.sync scores, 512 threads =======================
// 16 warps: 8 row-groups x 2 col-groups; each warp 16 q-rows x 64 key-cols.
// smem: Q 64KB | K0 64KB | K1 64KB | kvall[2048] float2 16KB | g3 rep 2560B | red 1KB
#define AT_Q   0
#define AT_K0  65536
#define AT_K1  131072
#define AT_KV  196608
#define AT_G3  212992
#define AT_RED 215552
#define ATTN_SMEM (216576 + 1024)

__global__ __launch_bounds__(512, 1) void attn_mma(const long long* __restrict__ pr,
                                                   const float* __restrict__ bs_p,
                                                   float* __restrict__ out) {
    extern __shared__ char dsm[];
    uint32_t base0 = s2u(dsm);
    uint32_t A0 = (base0 + 1023u) & ~1023u;
    char* P = dsm + (A0 - base0);

    const int t = threadIdx.x, w = t >> 5, lane = t & 31;
    const int wr = w >> 1, wc = w & 1;
    const int b = blockIdx.y, n0 = blockIdx.x * 128;

    const uint32_t SQ = A0 + AT_Q;
    const uint32_t SK[2] = { A0 + AT_K0, A0 + AT_K1 };
    float2* kvall = (float2*)(P + AT_KV);   // (s, rank-bits) for all 2048 keys
    float*  g3    = (float*)(P + AT_G3);    // gate LUT replicated 32x
    float*  redl  = (float*)(P + AT_RED);   // cross-warp (l,a) partials
    float*  reda  = redl + 128;

    // initial async loads: Q tile + K tile 0
    const __nv_bfloat16* qsrc = g_qb + ((size_t)b * NN + n0) * DOUT;
    const __nv_bfloat16* ksrc = g_kb + (size_t)b * NN * DOUT;
    #pragma unroll
    for (int it = 0; it < 8; it++) {
        int idx = t + it * 512;
        int r = idx >> 5, c = idx & 31;
        CP16(SQ + sw(r, c), qsrc + (size_t)r * DOUT + c * 8);
        CP16(SK[0] + sw(r, c), ksrc + (size_t)r * DOUT + c * 8);
    }
    CP_COMMIT();

    // kvall + gate LUT (regular loads, overlapped with cp.async)
    #pragma unroll
    for (int it = 0; it < 4; it++) {
        int idx = t + it * 512;
        kvall[idx] = make_float2(g_s[(size_t)b * NN + idx],
                                 __int_as_float((int)pr[(size_t)b * NN + idx]));
    }
    for (int i = t; i < NBUCK * 32; i += 512) g3[i] = g_gate3[i >> 5];

    const int w16 = wr * 16;
    const int rn0 = (int)pr[(size_t)b * NN + n0 + w16 + (lane >> 2)];
    const int rn1 = (int)pr[(size_t)b * NN + n0 + w16 + (lane >> 2) + 8];

    const uint32_t arow = (uint32_t)(w16 + ((lane >> 3) & 1) * 8 + (lane & 7));
    const uint32_t ac   = (uint32_t)((lane >> 4) & 1);
    const uint32_t brlo = (uint32_t)(wc * 64 + ((lane >> 4) & 1) * 8 + (lane & 7));
    const uint32_t bc   = (uint32_t)((lane >> 3) & 1);

    float l0 = 0.f, a0s = 0.f, l1 = 0.f, a1s = 0.f;

    CP_WAIT0();
    __syncthreads();

    for (int tile = 0; tile < 16; tile++) {
        const int buf = tile & 1;
        // prefetch next K tile (overlapped with mma+epilogue)
        if (tile + 1 < 16) {
            const __nv_bfloat16* kn = ksrc + (size_t)(tile + 1) * 128 * DOUT;
            #pragma unroll
            for (int it = 0; it < 8; it++) {
                int idx = t + it * 512;
                int r = idx >> 5, c = idx & 31;
                CP16(SK[1 - buf] + sw(r, c), kn + (size_t)r * DOUT + c * 8);
            }
            CP_COMMIT();
        }

        // ---- scores mma: acc[j] covers cols wc*64 + j*8 .. +7 of this 128-col tile ----
        float acc[8][4];
        #pragma unroll
        for (int j = 0; j < 8; j++) { acc[j][0]=0.f; acc[j][1]=0.f; acc[j][2]=0.f; acc[j][3]=0.f; }

        const uint32_t SKb = SK[buf];
        #pragma unroll
        for (int ks = 0; ks < 16; ks++) {
            uint32_t a0, a1, a2, a3;
            LDSM4(a0, a1, a2, a3, SQ + sw(arow, (uint32_t)(ks * 2) + ac));
            #pragma unroll
            for (int nb = 0; nb < 4; nb++) {
                uint32_t b0, b1, b2, b3;
                LDSM4(b0, b1, b2, b3, SKb + sw((uint32_t)(nb * 16) + brlo, (uint32_t)(ks * 2) + bc));
                mma16816(acc[nb * 2],     a0, a1, a2, a3, b0, b1);
                mma16816(acc[nb * 2 + 1], a0, a1, a2, a3, b2, b3);
            }
        }

        // ---- epilogue: gate + exp + accumulate (no-max softmax, bounded logits) ----
        const float2* kva = kvall + tile * 128;
        #pragma unroll
        for (int j = 0; j < 8; j++) {
            int col = wc * 64 + j * 8 + (lane & 3) * 2;
            float2 kv0 = kva[col];
            float2 kv1 = kva[col + 1];
            int rm0 = __float_as_int(kv0.y);
            int rm1 = __float_as_int(kv1.y);
            int d00 = rn0 - rm0; d00 = d00 < 0 ? -d00 : d00;
            int d01 = rn0 - rm1; d01 = d01 < 0 ? -d01 : d01;
            int d10 = rn1 - rm0; d10 = d10 < 0 ? -d10 : d10;
            int d11 = rn1 - rm1; d11 = d11 < 0 ? -d11 : d11;
            unsigned k00 = (unsigned)d00 / 5u; if (k00 > NBUCK-1) k00 = NBUCK-1;
            unsigned k01 = (unsigned)d01 / 5u; if (k01 > NBUCK-1) k01 = NBUCK-1;
            unsigned k10 = (unsigned)d10 / 5u; if (k10 > NBUCK-1) k10 = NBUCK-1;
            unsigned k11 = (unsigned)d11 / 5u; if (k11 > NBUCK-1) k11 = NBUCK-1;
            float e;
            e = exp2_fast(acc[j][0] * g3[k00 * 32 + lane]); l0 += e; a0s = fmaf(e, kv0.x, a0s);
            e = exp2_fast(acc[j][1] * g3[k01 * 32 + lane]); l0 += e; a0s = fmaf(e, kv1.x, a0s);
            e = exp2_fast(acc[j][2] * g3[k10 * 32 + lane]); l1 += e; a1s = fmaf(e, kv0.x, a1s);
            e = exp2_fast(acc[j][3] * g3[k11 * 32 + lane]); l1 += e; a1s = fmaf(e, kv1.x, a1s);
        }

        CP_WAIT0();
        __syncthreads();
    }

    // reduce over the 4 lanes sharing each row
    #pragma unroll
    for (int s = 1; s <= 2; s <<= 1) {
        l0  += __shfl_xor_sync(0xffffffffu, l0,  s);
        a0s += __shfl_xor_sync(0xffffffffu, a0s, s);
        l1  += __shfl_xor_sync(0xffffffffu, l1,  s);
        a1s += __shfl_xor_sync(0xffffffffu, a1s, s);
    }
    // cross-warp reduce between the two col-group warps of each row-group
    const int lr = w16 + (lane >> 2);
    if ((lane & 3) == 0 && wc == 0) {
        redl[lr] = l0;     reda[lr] = a0s;
        redl[lr + 8] = l1; reda[lr + 8] = a1s;
    }
    __syncthreads();
    if ((lane & 3) == 0 && wc == 1) {
        float bsv = bs_p[0];
        float L0 = l0 + redl[lr],     A0v = a0s + reda[lr];
        float L1 = l1 + redl[lr + 8], A1v = a1s + reda[lr + 8];
        float z0 = A0v / L0 + bsv;
        float z1 = A1v / L1 + bsv;
        out[(size_t)b * NN + n0 + lr]     = 1.f / (1.f + expf(-z0));
        out[(size_t)b * NN + n0 + lr + 8] = 1.f / (1.f + expf(-z1));
    }
}

// ======================= launcher =======================
extern "C" void kernel_launch(void* const* d_in, const int* in_sizes, int n_in,
                              void* d_out, int out_size) {
    const float*     x    = (const float*)d_in[0];
    const long long* pr   = (const long long*)d_in[1];
    const float*     Wq   = (const float*)d_in[2];
    const float*     bq   = (const float*)d_in[3];
    const float*     Wk   = (const float*)d_in[4];
    const float*     bk   = (const float*)d_in[5];
    const float*     Wv   = (const float*)d_in[6];
    const float*     bv   = (const float*)d_in[7];
    const float*     Ws   = (const float*)d_in[8];
    const float*     bs   = (const float*)d_in[9];
    const float*     remb = (const float*)d_in[10];
    const float*     rw   = (const float*)d_in[11];
    float* out = (float*)d_out;

    prep_kernel<<<1, 512>>>(Wv, bv, Ws, remb, rw);
    s_kernel<<<ROWS/8, 256>>>(x);

    cudaFuncSetAttribute(qk_mma, cudaFuncAttributeMaxDynamicSharedMemorySize, QK_SMEM);
    dim3 g1(ROWS/128, 4);
    qk_mma<<<g1, 512, QK_SMEM>>>(x, Wq, bq, Wk, bk);

    cudaFuncSetAttribute(attn_mma, cudaFuncAttributeMaxDynamicSharedMemorySize, ATTN_SMEM);
    dim3 g2(NN/128, BB);
    attn_mma<<<g2, 512, ATTN_SMEM>>>(pr, bs, out);
}

// round 9
// speedup vs baseline: 1.2043x; 1.2043x over previous
#include <cuda_runtime.h>
#include <cuda_bf16.h>
#include <stdint.h>
#include <math.h>

#define BB 8
#define NN 2048
#define DIN 512
#define DOUT 256
#define NBUCK 20
#define ROWS (BB*NN)   // 16384

// ---------------- scratch (static __device__, no allocations) ----------------
__device__ __nv_bfloat16 g_qb[ROWS*DOUT];    // q  (bf16)  8 MB
__device__ __nv_bfloat16 g_kb[ROWS*DOUT];    // k  (bf16)  8 MB
__device__ __nv_bfloat16 g_xb[ROWS*DIN];     // x  (bf16) 16 MB
__device__ __nv_bfloat16 g_wqb[DOUT*DIN];    // Wq (bf16)
__device__ __nv_bfloat16 g_wkb[DOUT*DIN];    // Wk (bf16)
__device__ float g_s[ROWS];
__device__ float g_gate3[NBUCK];             // sigmoid(rw*emb) * log2(e) / 16
__device__ float g_wvs[DIN];
__device__ float g_bvs;

// ======================= helpers =======================
__device__ __forceinline__ uint32_t s2u(const void* p) {
    return (uint32_t)__cvta_generic_to_shared(p);
}

// swizzled smem byte offset, 512B rows (32 chunks of 16B)  [128x256 bf16 tile]
__device__ __forceinline__ uint32_t sw(uint32_t row, uint32_t chunk) {
    return row * 512u + ((chunk ^ (row & 7u)) << 4);
}
// swizzled smem byte offset, 256B rows (16 chunks of 16B)  [128x128 bf16 tile]
__device__ __forceinline__ uint32_t sw2(uint32_t row, uint32_t chunk) {
    return row * 256u + ((chunk ^ (row & 7u)) << 4);
}

#define LDSM4(r0,r1,r2,r3,a)                                                     \
    asm volatile("ldmatrix.sync.aligned.m8n8.x4.shared.b16 {%0,%1,%2,%3}, [%4];" \
        : "=r"(r0), "=r"(r1), "=r"(r2), "=r"(r3) : "r"(a))

__device__ __forceinline__ void mma16816(float* c, uint32_t a0, uint32_t a1,
                                         uint32_t a2, uint32_t a3,
                                         uint32_t b0, uint32_t b1) {
    asm volatile("mma.sync.aligned.m16n8k16.row.col.f32.bf16.bf16.f32 "
        "{%0,%1,%2,%3}, {%4,%5,%6,%7}, {%8,%9}, {%0,%1,%2,%3};"
        : "+f"(c[0]), "+f"(c[1]), "+f"(c[2]), "+f"(c[3])
        : "r"(a0), "r"(a1), "r"(a2), "r"(a3), "r"(b0), "r"(b1));
}

#define CP16(dst, src) asm volatile("cp.async.cg.shared.global [%0], [%1], 16;" :: "r"(dst), "l"(src) : "memory")
#define CP_COMMIT()    asm volatile("cp.async.commit_group;" ::: "memory")
#define CP_WAIT0()     asm volatile("cp.async.wait_group 0;" ::: "memory")

// fast 2^y, deg-4, rel err ~4e-5, pure fma pipe
__device__ __forceinline__ float exp2_fast(float y) {
    float z = y + 12582912.0f;
    float f = y - (z - 12582912.0f);
    uint32_t n = (uint32_t)__float_as_int(z);
    float p = 9.6181291e-3f;
    p = fmaf(p, f, 5.5504109e-2f);
    p = fmaf(p, f, 2.4022652e-1f);
    p = fmaf(p, f, 6.9314718e-1f);
    p = fmaf(p, f, 1.0f);
    return __uint_as_float((n << 23) + 0x3f800000u) * p;
}

// ======================= fp32 -> bf16 convert (x, Wq, Wk) =======================
#define X4  (ROWS*DIN/4)        // float4 units in x
#define W4  (DOUT*DIN/4)        // float4 units per W
__global__ void to_bf16(const float* __restrict__ x, const float* __restrict__ Wq,
                        const float* __restrict__ Wk) {
    int total = X4 + 2 * W4;
    for (int i = blockIdx.x * blockDim.x + threadIdx.x; i < total; i += gridDim.x * blockDim.x) {
        const float* src; __nv_bfloat16* dst; int j;
        if (i < X4)            { src = x;  dst = g_xb;  j = i; }
        else if (i < X4 + W4)  { src = Wq; dst = g_wqb; j = i - X4; }
        else                   { src = Wk; dst = g_wkb; j = i - X4 - W4; }
        float4 v = *(const float4*)(src + (size_t)j * 4);
        __nv_bfloat162 h0 = __floats2bfloat162_rn(v.x, v.y);
        __nv_bfloat162 h1 = __floats2bfloat162_rn(v.z, v.w);
        uint2 u; u.x = *(uint32_t*)&h0; u.y = *(uint32_t*)&h1;
        *(uint2*)(dst + (size_t)j * 4) = u;
    }
}

// ======================= prep: gate LUT + bvs =======================
__global__ void prep_kernel(const float* __restrict__ bv, const float* __restrict__ Ws,
                            const float* __restrict__ remb, const float* __restrict__ rw) {
    int t = threadIdx.x;
    if (t < NBUCK) {
        float zv = rw[0] * remb[t];
        float sg = 1.f / (1.f + expf(-zv));
        g_gate3[t] = sg * (1.44269504088896f / 16.0f);  // fold log2e / sqrt(DOUT)
    }
    if (t < 32) {
        float acc = 0.f;
        #pragma unroll
        for (int o = t; o < DOUT; o += 32) acc += bv[o] * Ws[o];
        #pragma unroll
        for (int s = 16; s; s >>= 1) acc += __shfl_xor_sync(0xffffffffu, acc, s);
        if (t == 0) g_bvs = acc;
    }
}

// ======================= wvs[d] = sum_o Wv[o][d] * Ws[o]  (8 blocks x 64) =======================
__global__ void wvs_kernel(const float* __restrict__ Wv, const float* __restrict__ Ws) {
    int d = blockIdx.x * 64 + threadIdx.x;
    float acc = 0.f;
    #pragma unroll 8
    for (int o = 0; o < DOUT; o++) acc += Wv[(size_t)o * DIN + d] * __ldg(Ws + o);
    g_wvs[d] = acc;
}

// ======================= s[b,m] = x . wvs + bvs =======================
__global__ void s_kernel(const float* __restrict__ x) {
    int row  = blockIdx.x * 8 + (threadIdx.x >> 5);
    int lane = threadIdx.x & 31;
    const float4* xr = (const float4*)(x + (size_t)row * DIN);
    const float4* wv = (const float4*)g_wvs;
    float acc = 0.f;
    #pragma unroll
    for (int i = 0; i < 4; i++) {
        float4 a = xr[lane + i * 32];
        float4 b = wv[lane + i * 32];
        acc += a.x*b.x + a.y*b.y + a.z*b.z + a.w*b.w;
    }
    #pragma unroll
    for (int s = 16; s; s >>= 1) acc += __shfl_xor_sync(0xffffffffu, acc, s);
    if (lane == 0) g_s[row] = acc + g_bvs;
}

// ======================= QK projection: bf16 mma, cp.async chunked =======================
// C[128 rows,128 feats] = x[128,512].W[128,512]^T, K split into 4 chunks of 128,
// double-buffered. 16 warps in 4x4 grid: each warp 32 rows x 32 cols.
// smem: A0 32K | A1 32K | B0 32K | B1 32K
#define QK_SMEM (131072 + 1024)

__global__ __launch_bounds__(512, 1) void qk_mma(const float* __restrict__ bq,
                                                 const float* __restrict__ bk) {
    extern __shared__ char dsm[];
    uint32_t base0 = s2u(dsm);
    uint32_t A0 = (base0 + 1023u) & ~1023u;

    const int t = threadIdx.x, w = t >> 5, lane = t & 31;
    const int wr = w >> 2, wc = w & 3;
    const int row0 = blockIdx.x * 128;
    int yc = blockIdx.y;
    const __nv_bfloat16* Wb = (yc < 2) ? g_wqb : g_wkb;
    const float* bias        = (yc < 2) ? bq : bk;
    __nv_bfloat16* outp      = (yc < 2) ? g_qb : g_kb;
    const int col0 = (yc & 1) * 128;

    const uint32_t SA[2] = { A0, A0 + 32768 };
    const uint32_t SB[2] = { A0 + 65536, A0 + 98304 };
    const __nv_bfloat16* asrc = g_xb + (size_t)row0 * DIN;
    const __nv_bfloat16* bsrc = Wb + (size_t)col0 * DIN;

    const int r0 = wr * 32;
    const uint32_t arow = (uint32_t)(r0 + ((lane >> 3) & 1) * 8 + (lane & 7));
    const uint32_t ac   = (uint32_t)((lane >> 4) & 1);
    const uint32_t brlo = (uint32_t)(wc * 32 + ((lane >> 4) & 1) * 8 + (lane & 7));
    const uint32_t bc   = (uint32_t)((lane >> 3) & 1);

    float acc[8][4];
    #pragma unroll
    for (int j = 0; j < 8; j++) { acc[j][0]=0.f; acc[j][1]=0.f; acc[j][2]=0.f; acc[j][3]=0.f; }

    // prefetch chunk 0
    #pragma unroll
    for (int it = 0; it < 4; it++) {
        int idx = t + it * 512;          // 0..2047
        int r = idx >> 4, c = idx & 15;
        CP16(SA[0] + sw2(r, c), asrc + (size_t)r * DIN + c * 8);
        CP16(SB[0] + sw2(r, c), bsrc + (size_t)r * DIN + c * 8);
    }
    CP_COMMIT();
    CP_WAIT0();
    __syncthreads();

    for (int h = 0; h < 4; h++) {
        const int buf = h & 1;
        if (h + 1 < 4) {
            const int nb2 = 1 - buf;
            #pragma unroll
            for (int it = 0; it < 4; it++) {
                int idx = t + it * 512;
                int r = idx >> 4, c = idx & 15;
                CP16(SA[nb2] + sw2(r, c), asrc + (size_t)r * DIN + (h + 1) * 128 + c * 8);
                CP16(SB[nb2] + sw2(r, c), bsrc + (size_t)r * DIN + (h + 1) * 128 + c * 8);
            }
            CP_COMMIT();
        }

        #pragma unroll
        for (int ks = 0; ks < 8; ks++) {
            uint32_t a0,a1,a2,a3,a4,a5,a6,a7;
            LDSM4(a0,a1,a2,a3, SA[buf] + sw2(arow,      (uint32_t)(ks*2) + ac));
            LDSM4(a4,a5,a6,a7, SA[buf] + sw2(arow + 16, (uint32_t)(ks*2) + ac));
            uint32_t b0,b1,b2,b3,b4,b5,b6,b7;
            LDSM4(b0,b1,b2,b3, SB[buf] + sw2(brlo,      (uint32_t)(ks*2) + bc));
            LDSM4(b4,b5,b6,b7, SB[buf] + sw2(brlo + 16, (uint32_t)(ks*2) + bc));
            mma16816(acc[0], a0,a1,a2,a3, b0,b1);
            mma16816(acc[1], a0,a1,a2,a3, b2,b3);
            mma16816(acc[2], a0,a1,a2,a3, b4,b5);
            mma16816(acc[3], a0,a1,a2,a3, b6,b7);
            mma16816(acc[4], a4,a5,a6,a7, b0,b1);
            mma16816(acc[5], a4,a5,a6,a7, b2,b3);
            mma16816(acc[6], a4,a5,a6,a7, b4,b5);
            mma16816(acc[7], a4,a5,a6,a7, b6,b7);
        }
        CP_WAIT0();
        __syncthreads();
    }

    // epilogue: bias add, bf16 store
    #pragma unroll
    for (int rb = 0; rb < 2; rb++) {
        #pragma unroll
        for (int nb = 0; nb < 4; nb++) {
            const float* a4 = acc[rb * 4 + nb];
            int col = col0 + wc * 32 + nb * 8 + (lane & 3) * 2;
            float b0 = __ldg(bias + col), b1 = __ldg(bias + col + 1);
            int ra = row0 + r0 + rb * 16 + (lane >> 2);
            __nv_bfloat162 lo = __floats2bfloat162_rn(a4[0] + b0, a4[1] + b1);
            __nv_bfloat162 hi = __floats2bfloat162_rn(a4[2] + b0, a4[3] + b1);
            *(uint32_t*)(outp + (size_t)ra * DOUT + col)       = *(uint32_t*)&lo;
            *(uint32_t*)(outp + (size_t)(ra + 8) * DOUT + col) = *(uint32_t*)&hi;
        }
    }
}

// ======================= fused attention: mma.sync scores, 4x4 warp grid =======================
// smem: Q 64KB | K0 64KB | K1 64KB | kvall 16KB | g3 2560B | red 4096B
#define AT_Q   0
#define AT_K0  65536
#define AT_K1  131072
#define AT_KV  196608
#define AT_G3  212992
#define AT_RED 215552
#define ATTN_SMEM (219648 + 1024)

__global__ __launch_bounds__(512, 1) void attn_mma(const long long* __restrict__ pr,
                                                   const float* __restrict__ bs_p,
                                                   float* __restrict__ out) {
    extern __shared__ char dsm[];
    uint32_t base0 = s2u(dsm);
    uint32_t A0 = (base0 + 1023u) & ~1023u;
    char* P = dsm + (A0 - base0);

    const int t = threadIdx.x, w = t >> 5, lane = t & 31;
    const int wr = w >> 2, wc = w & 3;
    const int b = blockIdx.y, n0 = blockIdx.x * 128;

    const uint32_t SQ = A0 + AT_Q;
    const uint32_t SK[2] = { A0 + AT_K0, A0 + AT_K1 };
    float2* kvall = (float2*)(P + AT_KV);
    float*  g3    = (float*)(P + AT_G3);
    float*  redl  = (float*)(P + AT_RED);        // [4][128]
    float*  reda  = (float*)(P + AT_RED + 2048); // [4][128]

    // initial async loads: Q tile + K tile 0
    const __nv_bfloat16* qsrc = g_qb + ((size_t)b * NN + n0) * DOUT;
    const __nv_bfloat16* ksrc = g_kb + (size_t)b * NN * DOUT;
    #pragma unroll
    for (int it = 0; it < 8; it++) {
        int idx = t + it * 512;
        int r = idx >> 5, c = idx & 31;
        CP16(SQ + sw(r, c), qsrc + (size_t)r * DOUT + c * 8);
        CP16(SK[0] + sw(r, c), ksrc + (size_t)r * DOUT + c * 8);
    }
    CP_COMMIT();

    // kvall + gate LUT
    #pragma unroll
    for (int it = 0; it < 4; it++) {
        int idx = t + it * 512;
        kvall[idx] = make_float2(g_s[(size_t)b * NN + idx],
                                 __int_as_float((int)pr[(size_t)b * NN + idx]));
    }
    for (int i = t; i < NBUCK * 32; i += 512) g3[i] = g_gate3[i >> 5];

    const int r0 = wr * 32;
    unsigned rn[4];
    #pragma unroll
    for (int i = 0; i < 4; i++)
        rn[i] = (unsigned)(int)pr[(size_t)b * NN + n0 + r0 + (lane >> 2) + i * 8];

    const uint32_t arow = (uint32_t)(r0 + ((lane >> 3) & 1) * 8 + (lane & 7));
    const uint32_t ac   = (uint32_t)((lane >> 4) & 1);
    const uint32_t brlo = (uint32_t)(wc * 32 + ((lane >> 4) & 1) * 8 + (lane & 7));
    const uint32_t bc   = (uint32_t)((lane >> 3) & 1);

    float lac[4], aac[4];
    #pragma unroll
    for (int i = 0; i < 4; i++) { lac[i] = 0.f; aac[i] = 0.f; }

    CP_WAIT0();
    __syncthreads();

    for (int tile = 0; tile < 16; tile++) {
        const int buf = tile & 1;
        if (tile + 1 < 16) {
            const __nv_bfloat16* kn = ksrc + (size_t)(tile + 1) * 128 * DOUT;
            #pragma unroll
            for (int it = 0; it < 8; it++) {
                int idx = t + it * 512;
                int r = idx >> 5, c = idx & 31;
                CP16(SK[1 - buf] + sw(r, c), kn + (size_t)r * DOUT + c * 8);
            }
            CP_COMMIT();
        }

        // ---- scores mma: warp covers rows r0..r0+31, cols wc*32..+31 ----
        float acc[8][4];
        #pragma unroll
        for (int j = 0; j < 8; j++) { acc[j][0]=0.f; acc[j][1]=0.f; acc[j][2]=0.f; acc[j][3]=0.f; }

        const uint32_t SKb = SK[buf];
        #pragma unroll
        for (int ks = 0; ks < 16; ks++) {
            uint32_t a0,a1,a2,a3,a4,a5,a6,a7;
            LDSM4(a0,a1,a2,a3, SQ + sw(arow,      (uint32_t)(ks*2) + ac));
            LDSM4(a4,a5,a6,a7, SQ + sw(arow + 16, (uint32_t)(ks*2) + ac));
            uint32_t b0,b1,b2,b3,b4,b5,b6,b7;
            LDSM4(b0,b1,b2,b3, SKb + sw(brlo,      (uint32_t)(ks*2) + bc));
            LDSM4(b4,b5,b6,b7, SKb + sw(brlo + 16, (uint32_t)(ks*2) + bc));
            mma16816(acc[0], a0,a1,a2,a3, b0,b1);
            mma16816(acc[1], a0,a1,a2,a3, b2,b3);
            mma16816(acc[2], a0,a1,a2,a3, b4,b5);
            mma16816(acc[3], a0,a1,a2,a3, b6,b7);
            mma16816(acc[4], a4,a5,a6,a7, b0,b1);
            mma16816(acc[5], a4,a5,a6,a7, b2,b3);
            mma16816(acc[6], a4,a5,a6,a7, b4,b5);
            mma16816(acc[7], a4,a5,a6,a7, b6,b7);
        }

        // ---- epilogue: gate + exp + accumulate ----
        const float2* kva = kvall + tile * 128;
        #pragma unroll
        for (int rb = 0; rb < 2; rb++) {
            #pragma unroll
            for (int nb = 0; nb < 4; nb++) {
                const float* a4 = acc[rb * 4 + nb];
                int col = wc * 32 + nb * 8 + (lane & 3) * 2;
                float2 kv0 = kva[col];
                float2 kv1 = kva[col + 1];
                unsigned rm0 = (unsigned)__float_as_int(kv0.y);
                unsigned rm1 = (unsigned)__float_as_int(kv1.y);
                unsigned rA = rn[rb * 2], rB = rn[rb * 2 + 1];
                unsigned k00 = __usad(rA, rm0, 0u) / 5u; k00 = umin(k00, NBUCK - 1u);
                unsigned k01 = __usad(rA, rm1, 0u) / 5u; k01 = umin(k01, NBUCK - 1u);
                unsigned k10 = __usad(rB, rm0, 0u) / 5u; k10 = umin(k10, NBUCK - 1u);
                unsigned k11 = __usad(rB, rm1, 0u) / 5u; k11 = umin(k11, NBUCK - 1u);
                float e;
                e = exp2_fast(a4[0] * g3[k00 * 32 + lane]); lac[rb*2]   += e; aac[rb*2]   = fmaf(e, kv0.x, aac[rb*2]);
                e = exp2_fast(a4[1] * g3[k01 * 32 + lane]); lac[rb*2]   += e; aac[rb*2]   = fmaf(e, kv1.x, aac[rb*2]);
                e = exp2_fast(a4[2] * g3[k10 * 32 + lane]); lac[rb*2+1] += e; aac[rb*2+1] = fmaf(e, kv0.x, aac[rb*2+1]);
                e = exp2_fast(a4[3] * g3[k11 * 32 + lane]); lac[rb*2+1] += e; aac[rb*2+1] = fmaf(e, kv1.x, aac[rb*2+1]);
            }
        }

        CP_WAIT0();
        __syncthreads();
    }

    // intra-warp reduce over the 4 lanes sharing each row
    #pragma unroll
    for (int s = 1; s <= 2; s <<= 1) {
        #pragma unroll
        for (int i = 0; i < 4; i++) {
            lac[i] += __shfl_xor_sync(0xffffffffu, lac[i], s);
            aac[i] += __shfl_xor_sync(0xffffffffu, aac[i], s);
        }
    }
    if ((lane & 3) == 0) {
        #pragma unroll
        for (int i = 0; i < 4; i++) {
            int row = r0 + (lane >> 2) + i * 8;
            redl[wc * 128 + row] = lac[i];
            reda[wc * 128 + row] = aac[i];
        }
    }
    __syncthreads();
    if (t < 128) {
        float L = redl[t] + redl[128 + t] + redl[256 + t] + redl[384 + t];
        float A = reda[t] + reda[128 + t] + reda[256 + t] + reda[384 + t];
        float z = A / L + bs_p[0];
        out[(size_t)b * NN + n0 + t] = 1.f / (1.f + expf(-z));
    }
}

// ======================= launcher =======================
extern "C" void kernel_launch(void* const* d_in, const int* in_sizes, int n_in,
                              void* d_out, int out_size) {
    const float*     x    = (const float*)d_in[0];
    const long long* pr   = (const long long*)d_in[1];
    const float*     Wq   = (const float*)d_in[2];
    const float*     bq   = (const float*)d_in[3];
    const float*     Wk   = (const float*)d_in[4];
    const float*     bk   = (const float*)d_in[5];
    const float*     Wv   = (const float*)d_in[6];
    const float*     bv   = (const float*)d_in[7];
    const float*     Ws   = (const float*)d_in[8];
    const float*     bs   = (const float*)d_in[9];
    const float*     remb = (const float*)d_in[10];
    const float*     rw   = (const float*)d_in[11];
    float* out = (float*)d_out;

    to_bf16<<<1024, 256>>>(x, Wq, Wk);
    prep_kernel<<<1, 64>>>(bv, Ws, remb, rw);
    wvs_kernel<<<8, 64>>>(Wv, Ws);
    s_kernel<<<ROWS/8, 256>>>(x);

    cudaFuncSetAttribute(qk_mma, cudaFuncAttributeMaxDynamicSharedMemorySize, QK_SMEM);
    dim3 g1(ROWS/128, 4);
    qk_mma<<<g1, 512, QK_SMEM>>>(bq, bk);

    cudaFuncSetAttribute(attn_mma, cudaFuncAttributeMaxDynamicSharedMemorySize, ATTN_SMEM);
    dim3 g2(NN/128, BB);
    attn_mma<<<g2, 512, ATTN_SMEM>>>(pr, bs, out);
}

// round 10
// speedup vs baseline: 1.2450x; 1.0338x over previous
#include <cuda_runtime.h>
#include <cuda_bf16.h>
#include <stdint.h>
#include <math.h>

#define BB 8
#define NN 2048
#define DIN 512
#define DOUT 256
#define NBUCK 20
#define ROWS (BB*NN)   // 16384

// ---------------- scratch (static __device__, no allocations) ----------------
__device__ __nv_bfloat16 g_qb[ROWS*DOUT];    // q  (bf16)  8 MB
__device__ __nv_bfloat16 g_kb[ROWS*DOUT];    // k  (bf16)  8 MB
__device__ __nv_bfloat16 g_xb[ROWS*DIN];     // x  (bf16) 16 MB
__device__ __nv_bfloat16 g_wqb[DOUT*DIN];    // Wq (bf16)
__device__ __nv_bfloat16 g_wkb[DOUT*DIN];    // Wk (bf16)
__device__ float g_s[ROWS];
__device__ float g_gate3[NBUCK];             // sigmoid(rw*emb) * log2(e) / 16
__device__ float g_wvs[DIN];
__device__ float g_bvs;

// ======================= helpers =======================
__device__ __forceinline__ uint32_t s2u(const void* p) {
    return (uint32_t)__cvta_generic_to_shared(p);
}

// swizzled smem byte offset, 512B rows (32 chunks of 16B)  [128x256 bf16 tile]
__device__ __forceinline__ uint32_t sw(uint32_t row, uint32_t chunk) {
    return row * 512u + ((chunk ^ (row & 7u)) << 4);
}
// swizzled smem byte offset, 256B rows (16 chunks of 16B)  [128x128 bf16 tile]
__device__ __forceinline__ uint32_t sw2(uint32_t row, uint32_t chunk) {
    return row * 256u + ((chunk ^ (row & 7u)) << 4);
}

#define LDSM4(r0,r1,r2,r3,a)                                                     \
    asm volatile("ldmatrix.sync.aligned.m8n8.x4.shared.b16 {%0,%1,%2,%3}, [%4];" \
        : "=r"(r0), "=r"(r1), "=r"(r2), "=r"(r3) : "r"(a))

__device__ __forceinline__ void mma16816(float* c, uint32_t a0, uint32_t a1,
                                         uint32_t a2, uint32_t a3,
                                         uint32_t b0, uint32_t b1) {
    asm volatile("mma.sync.aligned.m16n8k16.row.col.f32.bf16.bf16.f32 "
        "{%0,%1,%2,%3}, {%4,%5,%6,%7}, {%8,%9}, {%0,%1,%2,%3};"
        : "+f"(c[0]), "+f"(c[1]), "+f"(c[2]), "+f"(c[3])
        : "r"(a0), "r"(a1), "r"(a2), "r"(a3), "r"(b0), "r"(b1));
}

#define CP16(dst, src) asm volatile("cp.async.cg.shared.global [%0], [%1], 16;" :: "r"(dst), "l"(src) : "memory")
#define CP_COMMIT()    asm volatile("cp.async.commit_group;" ::: "memory")
#define CP_WAIT0()     asm volatile("cp.async.wait_group 0;" ::: "memory")

// fast 2^y, deg-4, rel err ~4e-5, pure fma pipe
__device__ __forceinline__ float exp2_fast(float y) {
    float z = y + 12582912.0f;
    float f = y - (z - 12582912.0f);
    uint32_t n = (uint32_t)__float_as_int(z);
    float p = 9.6181291e-3f;
    p = fmaf(p, f, 5.5504109e-2f);
    p = fmaf(p, f, 2.4022652e-1f);
    p = fmaf(p, f, 6.9314718e-1f);
    p = fmaf(p, f, 1.0f);
    return __uint_as_float((n << 23) + 0x3f800000u) * p;
}

// ======================= prep: wvs GEMV + gate LUT + bvs (one launch) =======================
// blocks 0..7: wvs[d] = sum_o Wv[o][d]*Ws[o]  (64 d's per block)
// block 8:     gate LUT + bvs
__global__ void prep_all(const float* __restrict__ Wv, const float* __restrict__ bv,
                         const float* __restrict__ Ws, const float* __restrict__ remb,
                         const float* __restrict__ rw) {
    int blk = blockIdx.x, t = threadIdx.x;
    if (blk < 8) {
        int d = blk * 64 + t;
        float acc = 0.f;
        #pragma unroll 8
        for (int o = 0; o < DOUT; o++) acc += Wv[(size_t)o * DIN + d] * __ldg(Ws + o);
        g_wvs[d] = acc;
    } else {
        if (t < NBUCK) {
            float zv = rw[0] * remb[t];
            float sg = 1.f / (1.f + expf(-zv));
            g_gate3[t] = sg * (1.44269504088896f / 16.0f);  // fold log2e / sqrt(DOUT)
        }
        if (t >= 32 && t < 64) {
            int l = t - 32;
            float acc = 0.f;
            #pragma unroll
            for (int o = l; o < DOUT; o += 32) acc += bv[o] * Ws[o];
            #pragma unroll
            for (int s = 16; s; s >>= 1) acc += __shfl_xor_sync(0xffffffffu, acc, s);
            if (l == 0) g_bvs = acc;
        }
    }
}

// ======================= weight fp32 -> bf16 =======================
#define W4 (DOUT*DIN/4)
__global__ void wconv(const float* __restrict__ Wq, const float* __restrict__ Wk) {
    for (int i = blockIdx.x * blockDim.x + threadIdx.x; i < 2 * W4; i += gridDim.x * blockDim.x) {
        const float* src = (i < W4) ? Wq : Wk;
        __nv_bfloat16* dst = (i < W4) ? g_wqb : g_wkb;
        int j = (i < W4) ? i : i - W4;
        float4 v = *(const float4*)(src + (size_t)j * 4);
        __nv_bfloat162 h0 = __floats2bfloat162_rn(v.x, v.y);
        __nv_bfloat162 h1 = __floats2bfloat162_rn(v.z, v.w);
        uint2 u; u.x = *(uint32_t*)&h0; u.y = *(uint32_t*)&h1;
        *(uint2*)(dst + (size_t)j * 4) = u;
    }
}

// ======================= fused x convert + s: one warp per row =======================
// reads x row fp32 once; writes bf16 row AND s[row] = x.wvs + bvs
__global__ void xs_kernel(const float* __restrict__ x) {
    int row  = blockIdx.x * 8 + (threadIdx.x >> 5);
    int lane = threadIdx.x & 31;
    const float4* xr = (const float4*)(x + (size_t)row * DIN);
    const float4* wv = (const float4*)g_wvs;
    uint2* xb = (uint2*)(g_xb + (size_t)row * DIN);
    float acc = 0.f;
    #pragma unroll
    for (int i = 0; i < 4; i++) {
        int idx = lane + i * 32;
        float4 a = xr[idx];
        float4 b = wv[idx];
        acc += a.x*b.x + a.y*b.y + a.z*b.z + a.w*b.w;
        __nv_bfloat162 h0 = __floats2bfloat162_rn(a.x, a.y);
        __nv_bfloat162 h1 = __floats2bfloat162_rn(a.z, a.w);
        uint2 u; u.x = *(uint32_t*)&h0; u.y = *(uint32_t*)&h1;
        xb[idx] = u;
    }
    #pragma unroll
    for (int s = 16; s; s >>= 1) acc += __shfl_xor_sync(0xffffffffu, acc, s);
    if (lane == 0) g_s[row] = acc + g_bvs;
}

// ======================= QK projection: bf16 mma, cp.async chunked =======================
// C[128 rows,128 feats] = x[128,512].W[128,512]^T, K split into 4 chunks of 128,
// double-buffered. 16 warps in 4x4 grid: each warp 32 rows x 32 cols.
#define QK_SMEM (131072 + 1024)

__global__ __launch_bounds__(512, 1) void qk_mma(const float* __restrict__ bq,
                                                 const float* __restrict__ bk) {
    extern __shared__ char dsm[];
    uint32_t base0 = s2u(dsm);
    uint32_t A0 = (base0 + 1023u) & ~1023u;

    const int t = threadIdx.x, w = t >> 5, lane = t & 31;
    const int wr = w >> 2, wc = w & 3;
    const int row0 = blockIdx.x * 128;
    int yc = blockIdx.y;
    const __nv_bfloat16* Wb = (yc < 2) ? g_wqb : g_wkb;
    const float* bias        = (yc < 2) ? bq : bk;
    __nv_bfloat16* outp      = (yc < 2) ? g_qb : g_kb;
    const int col0 = (yc & 1) * 128;

    const uint32_t SA[2] = { A0, A0 + 32768 };
    const uint32_t SB[2] = { A0 + 65536, A0 + 98304 };
    const __nv_bfloat16* asrc = g_xb + (size_t)row0 * DIN;
    const __nv_bfloat16* bsrc = Wb + (size_t)col0 * DIN;

    const int r0 = wr * 32;
    const uint32_t arow = (uint32_t)(r0 + ((lane >> 3) & 1) * 8 + (lane & 7));
    const uint32_t ac   = (uint32_t)((lane >> 4) & 1);
    const uint32_t brlo = (uint32_t)(wc * 32 + ((lane >> 4) & 1) * 8 + (lane & 7));
    const uint32_t bc   = (uint32_t)((lane >> 3) & 1);

    float acc[8][4];
    #pragma unroll
    for (int j = 0; j < 8; j++) { acc[j][0]=0.f; acc[j][1]=0.f; acc[j][2]=0.f; acc[j][3]=0.f; }

    // prefetch chunk 0
    #pragma unroll
    for (int it = 0; it < 4; it++) {
        int idx = t + it * 512;
        int r = idx >> 4, c = idx & 15;
        CP16(SA[0] + sw2(r, c), asrc + (size_t)r * DIN + c * 8);
        CP16(SB[0] + sw2(r, c), bsrc + (size_t)r * DIN + c * 8);
    }
    CP_COMMIT();
    CP_WAIT0();
    __syncthreads();

    for (int h = 0; h < 4; h++) {
        const int buf = h & 1;
        if (h + 1 < 4) {
            const int nb2 = 1 - buf;
            #pragma unroll
            for (int it = 0; it < 4; it++) {
                int idx = t + it * 512;
                int r = idx >> 4, c = idx & 15;
                CP16(SA[nb2] + sw2(r, c), asrc + (size_t)r * DIN + (h + 1) * 128 + c * 8);
                CP16(SB[nb2] + sw2(r, c), bsrc + (size_t)r * DIN + (h + 1) * 128 + c * 8);
            }
            CP_COMMIT();
        }

        #pragma unroll
        for (int ks = 0; ks < 8; ks++) {
            uint32_t a0,a1,a2,a3,a4,a5,a6,a7;
            LDSM4(a0,a1,a2,a3, SA[buf] + sw2(arow,      (uint32_t)(ks*2) + ac));
            LDSM4(a4,a5,a6,a7, SA[buf] + sw2(arow + 16, (uint32_t)(ks*2) + ac));
            uint32_t b0,b1,b2,b3,b4,b5,b6,b7;
            LDSM4(b0,b1,b2,b3, SB[buf] + sw2(brlo,      (uint32_t)(ks*2) + bc));
            LDSM4(b4,b5,b6,b7, SB[buf] + sw2(brlo + 16, (uint32_t)(ks*2) + bc));
            mma16816(acc[0], a0,a1,a2,a3, b0,b1);
            mma16816(acc[1], a0,a1,a2,a3, b2,b3);
            mma16816(acc[2], a0,a1,a2,a3, b4,b5);
            mma16816(acc[3], a0,a1,a2,a3, b6,b7);
            mma16816(acc[4], a4,a5,a6,a7, b0,b1);
            mma16816(acc[5], a4,a5,a6,a7, b2,b3);
            mma16816(acc[6], a4,a5,a6,a7, b4,b5);
            mma16816(acc[7], a4,a5,a6,a7, b6,b7);
        }
        CP_WAIT0();
        __syncthreads();
    }

    // epilogue: bias add, bf16 store
    #pragma unroll
    for (int rb = 0; rb < 2; rb++) {
        #pragma unroll
        for (int nb = 0; nb < 4; nb++) {
            const float* a4 = acc[rb * 4 + nb];
            int col = col0 + wc * 32 + nb * 8 + (lane & 3) * 2;
            float b0 = __ldg(bias + col), b1 = __ldg(bias + col + 1);
            int ra = row0 + r0 + rb * 16 + (lane >> 2);
            __nv_bfloat162 lo = __floats2bfloat162_rn(a4[0] + b0, a4[1] + b1);
            __nv_bfloat162 hi = __floats2bfloat162_rn(a4[2] + b0, a4[3] + b1);
            *(uint32_t*)(outp + (size_t)ra * DOUT + col)       = *(uint32_t*)&lo;
            *(uint32_t*)(outp + (size_t)(ra + 8) * DOUT + col) = *(uint32_t*)&hi;
        }
    }
}

// ======================= fused attention: mma.sync scores, 4x4 warp grid =======================
// smem: Q 64KB | K0 64KB | K1 64KB | kvall 16KB | g3 2560B | red 4096B
#define AT_Q   0
#define AT_K0  65536
#define AT_K1  131072
#define AT_KV  196608
#define AT_G3  212992
#define AT_RED 215552
#define ATTN_SMEM (219648 + 1024)

__global__ __launch_bounds__(512, 1) void attn_mma(const long long* __restrict__ pr,
                                                   const float* __restrict__ bs_p,
                                                   float* __restrict__ out) {
    extern __shared__ char dsm[];
    uint32_t base0 = s2u(dsm);
    uint32_t A0 = (base0 + 1023u) & ~1023u;
    char* P = dsm + (A0 - base0);

    const int t = threadIdx.x, w = t >> 5, lane = t & 31;
    const int wr = w >> 2, wc = w & 3;
    const int b = blockIdx.y, n0 = blockIdx.x * 128;

    const uint32_t SQ = A0 + AT_Q;
    const uint32_t SK[2] = { A0 + AT_K0, A0 + AT_K1 };
    float2* kvall = (float2*)(P + AT_KV);
    float*  g3    = (float*)(P + AT_G3);
    float*  redl  = (float*)(P + AT_RED);        // [4][128]
    float*  reda  = (float*)(P + AT_RED + 2048); // [4][128]

    // initial async loads: Q tile + K tile 0
    const __nv_bfloat16* qsrc = g_qb + ((size_t)b * NN + n0) * DOUT;
    const __nv_bfloat16* ksrc = g_kb + (size_t)b * NN * DOUT;
    #pragma unroll
    for (int it = 0; it < 8; it++) {
        int idx = t + it * 512;
        int r = idx >> 5, c = idx & 31;
        CP16(SQ + sw(r, c), qsrc + (size_t)r * DOUT + c * 8);
        CP16(SK[0] + sw(r, c), ksrc + (size_t)r * DOUT + c * 8);
    }
    CP_COMMIT();

    // kvall + gate LUT
    #pragma unroll
    for (int it = 0; it < 4; it++) {
        int idx = t + it * 512;
        kvall[idx] = make_float2(g_s[(size_t)b * NN + idx],
                                 __int_as_float((int)pr[(size_t)b * NN + idx]));
    }
    for (int i = t; i < NBUCK * 32; i += 512) g3[i] = g_gate3[i >> 5];

    const int r0 = wr * 32;
    unsigned rn[4];
    #pragma unroll
    for (int i = 0; i < 4; i++)
        rn[i] = (unsigned)(int)pr[(size_t)b * NN + n0 + r0 + (lane >> 2) + i * 8];

    const uint32_t arow = (uint32_t)(r0 + ((lane >> 3) & 1) * 8 + (lane & 7));
    const uint32_t ac   = (uint32_t)((lane >> 4) & 1);
    const uint32_t brlo = (uint32_t)(wc * 32 + ((lane >> 4) & 1) * 8 + (lane & 7));
    const uint32_t bc   = (uint32_t)((lane >> 3) & 1);

    float lac[4], aac[4];
    #pragma unroll
    for (int i = 0; i < 4; i++) { lac[i] = 0.f; aac[i] = 0.f; }

    CP_WAIT0();
    __syncthreads();

    for (int tile = 0; tile < 16; tile++) {
        const int buf = tile & 1;
        if (tile + 1 < 16) {
            const __nv_bfloat16* kn = ksrc + (size_t)(tile + 1) * 128 * DOUT;
            #pragma unroll
            for (int it = 0; it < 8; it++) {
                int idx = t + it * 512;
                int r = idx >> 5, c = idx & 31;
                CP16(SK[1 - buf] + sw(r, c), kn + (size_t)r * DOUT + c * 8);
            }
            CP_COMMIT();
        }

        // ---- scores mma: warp covers rows r0..r0+31, cols wc*32..+31 ----
        float acc[8][4];
        #pragma unroll
        for (int j = 0; j < 8; j++) { acc[j][0]=0.f; acc[j][1]=0.f; acc[j][2]=0.f; acc[j][3]=0.f; }

        const uint32_t SKb = SK[buf];
        #pragma unroll
        for (int ks = 0; ks < 16; ks++) {
            uint32_t a0,a1,a2,a3,a4,a5,a6,a7;
            LDSM4(a0,a1,a2,a3, SQ + sw(arow,      (uint32_t)(ks*2) + ac));
            LDSM4(a4,a5,a6,a7, SQ + sw(arow + 16, (uint32_t)(ks*2) + ac));
            uint32_t b0,b1,b2,b3,b4,b5,b6,b7;
            LDSM4(b0,b1,b2,b3, SKb + sw(brlo,      (uint32_t)(ks*2) + bc));
            LDSM4(b4,b5,b6,b7, SKb + sw(brlo + 16, (uint32_t)(ks*2) + bc));
            mma16816(acc[0], a0,a1,a2,a3, b0,b1);
            mma16816(acc[1], a0,a1,a2,a3, b2,b3);
            mma16816(acc[2], a0,a1,a2,a3, b4,b5);
            mma16816(acc[3], a0,a1,a2,a3, b6,b7);
            mma16816(acc[4], a4,a5,a6,a7, b0,b1);
            mma16816(acc[5], a4,a5,a6,a7, b2,b3);
            mma16816(acc[6], a4,a5,a6,a7, b4,b5);
            mma16816(acc[7], a4,a5,a6,a7, b6,b7);
        }

        // ---- epilogue: nb outer so kv loads + rank converts are shared across rb ----
        const float2* kva = kvall + tile * 128;
        #pragma unroll
        for (int nb = 0; nb < 4; nb++) {
            int col = wc * 32 + nb * 8 + (lane & 3) * 2;
            float2 kv0 = kva[col];
            float2 kv1 = kva[col + 1];
            unsigned rm0 = (unsigned)__float_as_int(kv0.y);
            unsigned rm1 = (unsigned)__float_as_int(kv1.y);
            #pragma unroll
            for (int rb = 0; rb < 2; rb++) {
                const float* a4 = acc[rb * 4 + nb];
                unsigned rA = rn[rb * 2], rB = rn[rb * 2 + 1];
                unsigned k00 = __usad(rA, rm0, 0u) / 5u; k00 = umin(k00, NBUCK - 1u);
                unsigned k01 = __usad(rA, rm1, 0u) / 5u; k01 = umin(k01, NBUCK - 1u);
                unsigned k10 = __usad(rB, rm0, 0u) / 5u; k10 = umin(k10, NBUCK - 1u);
                unsigned k11 = __usad(rB, rm1, 0u) / 5u; k11 = umin(k11, NBUCK - 1u);
                float e;
                e = exp2_fast(a4[0] * g3[k00 * 32 + lane]); lac[rb*2]   += e; aac[rb*2]   = fmaf(e, kv0.x, aac[rb*2]);
                e = exp2_fast(a4[1] * g3[k01 * 32 + lane]); lac[rb*2]   += e; aac[rb*2]   = fmaf(e, kv1.x, aac[rb*2]);
                e = exp2_fast(a4[2] * g3[k10 * 32 + lane]); lac[rb*2+1] += e; aac[rb*2+1] = fmaf(e, kv0.x, aac[rb*2+1]);
                e = exp2_fast(a4[3] * g3[k11 * 32 + lane]); lac[rb*2+1] += e; aac[rb*2+1] = fmaf(e, kv1.x, aac[rb*2+1]);
            }
        }

        CP_WAIT0();
        __syncthreads();
    }

    // intra-warp reduce over the 4 lanes sharing each row
    #pragma unroll
    for (int s = 1; s <= 2; s <<= 1) {
        #pragma unroll
        for (int i = 0; i < 4; i++) {
            lac[i] += __shfl_xor_sync(0xffffffffu, lac[i], s);
            aac[i] += __shfl_xor_sync(0xffffffffu, aac[i], s);
        }
    }
    if ((lane & 3) == 0) {
        #pragma unroll
        for (int i = 0; i < 4; i++) {
            int row = r0 + (lane >> 2) + i * 8;
            redl[wc * 128 + row] = lac[i];
            reda[wc * 128 + row] = aac[i];
        }
    }
    __syncthreads();
    if (t < 128) {
        float L = redl[t] + redl[128 + t] + redl[256 + t] + redl[384 + t];
        float A = reda[t] + reda[128 + t] + reda[256 + t] + reda[384 + t];
        float z = A / L + bs_p[0];
        out[(size_t)b * NN + n0 + t] = 1.f / (1.f + expf(-z));
    }
}

// ======================= launcher =======================
extern "C" void kernel_launch(void* const* d_in, const int* in_sizes, int n_in,
                              void* d_out, int out_size) {
    const float*     x    = (const float*)d_in[0];
    const long long* pr   = (const long long*)d_in[1];
    const float*     Wq   = (const float*)d_in[2];
    const float*     bq   = (const float*)d_in[3];
    const float*     Wk   = (const float*)d_in[4];
    const float*     bk   = (const float*)d_in[5];
    const float*     Wv   = (const float*)d_in[6];
    const float*     bv   = (const float*)d_in[7];
    const float*     Ws   = (const float*)d_in[8];
    const float*     bs   = (const float*)d_in[9];
    const float*     remb = (const float*)d_in[10];
    const float*     rw   = (const float*)d_in[11];
    float* out = (float*)d_out;

    prep_all<<<9, 64>>>(Wv, bv, Ws, remb, rw);        // wvs + gate + bvs
    wconv<<<256, 256>>>(Wq, Wk);                      // weights -> bf16
    xs_kernel<<<ROWS/8, 256>>>(x);                    // x -> bf16 fused with s

    cudaFuncSetAttribute(qk_mma, cudaFuncAttributeMaxDynamicSharedMemorySize, QK_SMEM);
    dim3 g1(ROWS/128, 4);
    qk_mma<<<g1, 512, QK_SMEM>>>(bq, bk);

    cudaFuncSetAttribute(attn_mma, cudaFuncAttributeMaxDynamicSharedMemorySize, ATTN_SMEM);
    dim3 g2(NN/128, BB);
    attn_mma<<<g2, 512, ATTN_SMEM>>>(pr, bs, out);
}

// round 14
// speedup vs baseline: 1.2708x; 1.0207x over previous
#include <cuda_runtime.h>
#include <cuda_bf16.h>
#include <stdint.h>
#include <math.h>

#define BB 8
#define NN 2048
#define DIN 512
#define DOUT 256
#define NBUCK 20
#define ROWS (BB*NN)   // 16384

// ---------------- scratch (static __device__, no allocations) ----------------
__device__ __nv_bfloat16 g_qb[ROWS*DOUT];    // q  (bf16)  8 MB
__device__ __nv_bfloat16 g_kb[ROWS*DOUT];    // k  (bf16)  8 MB
__device__ __nv_bfloat16 g_xb[ROWS*DIN];     // x  (bf16) 16 MB
__device__ __nv_bfloat16 g_wqb[DOUT*DIN];    // Wq (bf16)
__device__ __nv_bfloat16 g_wkb[DOUT*DIN];    // Wk (bf16)
__device__ float g_s[ROWS];
__device__ float g_gate3[NBUCK];             // sigmoid(rw*emb) * log2(e) / 16
__device__ float g_wvs[DIN];
__device__ float g_bvs;

// ======================= helpers =======================
__device__ __forceinline__ uint32_t s2u(const void* p) {
    return (uint32_t)__cvta_generic_to_shared(p);
}

// swizzled smem byte offset, 512B rows (32 chunks of 16B)  [128x256 bf16 tile]
__device__ __forceinline__ uint32_t sw(uint32_t row, uint32_t chunk) {
    return row * 512u + ((chunk ^ (row & 7u)) << 4);
}
// swizzled smem byte offset, 256B rows (16 chunks of 16B)  [128x128 bf16 tile]
__device__ __forceinline__ uint32_t sw2(uint32_t row, uint32_t chunk) {
    return row * 256u + ((chunk ^ (row & 7u)) << 4);
}

#define LDSM4(r0,r1,r2,r3,a)                                                     \
    asm volatile("ldmatrix.sync.aligned.m8n8.x4.shared.b16 {%0,%1,%2,%3}, [%4];" \
        : "=r"(r0), "=r"(r1), "=r"(r2), "=r"(r3) : "r"(a))

__device__ __forceinline__ void mma16816(float* c, uint32_t a0, uint32_t a1,
                                         uint32_t a2, uint32_t a3,
                                         uint32_t b0, uint32_t b1) {
    asm volatile("mma.sync.aligned.m16n8k16.row.col.f32.bf16.bf16.f32 "
        "{%0,%1,%2,%3}, {%4,%5,%6,%7}, {%8,%9}, {%0,%1,%2,%3};"
        : "+f"(c[0]), "+f"(c[1]), "+f"(c[2]), "+f"(c[3])
        : "r"(a0), "r"(a1), "r"(a2), "r"(a3), "r"(b0), "r"(b1));
}

#define CP16(dst, src) asm volatile("cp.async.cg.shared.global [%0], [%1], 16;" :: "r"(dst), "l"(src) : "memory")
#define CP_COMMIT()    asm volatile("cp.async.commit_group;" ::: "memory")
#define CP_WAIT0()     asm volatile("cp.async.wait_group 0;" ::: "memory")
#define CP_WAIT1()     asm volatile("cp.async.wait_group 1;" ::: "memory")

// fast 2^y, deg-4, rel err ~4e-5, pure fma pipe
__device__ __forceinline__ float exp2_fast(float y) {
    float z = y + 12582912.0f;
    float f = y - (z - 12582912.0f);
    uint32_t n = (uint32_t)__float_as_int(z);
    float p = 9.6181291e-3f;
    p = fmaf(p, f, 5.5504109e-2f);
    p = fmaf(p, f, 2.4022652e-1f);
    p = fmaf(p, f, 6.9314718e-1f);
    p = fmaf(p, f, 1.0f);
    return __uint_as_float((n << 23) + 0x3f800000u) * p;
}

// ======================= prep: wvs GEMV + gate LUT + bvs (one launch) =======================
__global__ void prep_all(const float* __restrict__ Wv, const float* __restrict__ bv,
                         const float* __restrict__ Ws, const float* __restrict__ remb,
                         const float* __restrict__ rw) {
    int blk = blockIdx.x, t = threadIdx.x;
    if (blk < 8) {
        int d = blk * 64 + t;
        float acc = 0.f;
        #pragma unroll 8
        for (int o = 0; o < DOUT; o++) acc += Wv[(size_t)o * DIN + d] * __ldg(Ws + o);
        g_wvs[d] = acc;
    } else {
        if (t < NBUCK) {
            float zv = rw[0] * remb[t];
            float sg = 1.f / (1.f + expf(-zv));
            g_gate3[t] = sg * (1.44269504088896f / 16.0f);  // fold log2e / sqrt(DOUT)
        }
        if (t >= 32 && t < 64) {
            int l = t - 32;
            float acc = 0.f;
            #pragma unroll
            for (int o = l; o < DOUT; o += 32) acc += bv[o] * Ws[o];
            #pragma unroll
            for (int s = 16; s; s >>= 1) acc += __shfl_xor_sync(0xffffffffu, acc, s);
            if (l == 0) g_bvs = acc;
        }
    }
}

// ======================= weight fp32 -> bf16 =======================
#define W4 (DOUT*DIN/4)
__global__ void wconv(const float* __restrict__ Wq, const float* __restrict__ Wk) {
    for (int i = blockIdx.x * blockDim.x + threadIdx.x; i < 2 * W4; i += gridDim.x * blockDim.x) {
        const float* src = (i < W4) ? Wq : Wk;
        __nv_bfloat16* dst = (i < W4) ? g_wqb : g_wkb;
        int j = (i < W4) ? i : i - W4;
        float4 v = *(const float4*)(src + (size_t)j * 4);
        __nv_bfloat162 h0 = __floats2bfloat162_rn(v.x, v.y);
        __nv_bfloat162 h1 = __floats2bfloat162_rn(v.z, v.w);
        uint2 u; u.x = *(uint32_t*)&h0; u.y = *(uint32_t*)&h1;
        *(uint2*)(dst + (size_t)j * 4) = u;
    }
}

// ======================= fused x convert + s: one warp per row =======================
__global__ void xs_kernel(const float* __restrict__ x) {
    int row  = blockIdx.x * 8 + (threadIdx.x >> 5);
    int lane = threadIdx.x & 31;
    const float4* xr = (const float4*)(x + (size_t)row * DIN);
    const float4* wv = (const float4*)g_wvs;
    uint2* xb = (uint2*)(g_xb + (size_t)row * DIN);
    float acc = 0.f;
    #pragma unroll
    for (int i = 0; i < 4; i++) {
        int idx = lane + i * 32;
        float4 a = xr[idx];
        float4 b = wv[idx];
        acc += a.x*b.x + a.y*b.y + a.z*b.z + a.w*b.w;
        __nv_bfloat162 h0 = __floats2bfloat162_rn(a.x, a.y);
        __nv_bfloat162 h1 = __floats2bfloat162_rn(a.z, a.w);
        uint2 u; u.x = *(uint32_t*)&h0; u.y = *(uint32_t*)&h1;
        xb[idx] = u;
    }
    #pragma unroll
    for (int s = 16; s; s >>= 1) acc += __shfl_xor_sync(0xffffffffu, acc, s);
    if (lane == 0) g_s[row] = acc + g_bvs;
}

// ======================= QK projection: persistent-A, single wave =======================
// Grid 128 CTAs. Each CTA: A = x[128,512] resident in smem (4 chunks of 32KB),
// computes 4 output tiles (Q cols 0/1, K cols 0/1) streaming B through 2 buffers.
// 16 iterations (yc,h); cp.async.wait_group 1 keeps one prefetch in flight.
#define QKP_SMEM (196608 + 1024)

__global__ __launch_bounds__(512, 1) void qk_mma(const float* __restrict__ bq,
                                                 const float* __restrict__ bk) {
    extern __shared__ char dsm[];
    uint32_t base0 = s2u(dsm);
    uint32_t A0 = (base0 + 1023u) & ~1023u;

    const int t = threadIdx.x, w = t >> 5, lane = t & 31;
    const int wr = w >> 2, wc = w & 3;
    const int row0 = blockIdx.x * 128;

    const uint32_t SB[2] = { A0 + 131072, A0 + 163840 };
    const __nv_bfloat16* asrc = g_xb + (size_t)row0 * DIN;

    const int r0 = wr * 32;
    const uint32_t arow = (uint32_t)(r0 + ((lane >> 3) & 1) * 8 + (lane & 7));
    const uint32_t ac   = (uint32_t)((lane >> 4) & 1);
    const uint32_t brlo = (uint32_t)(wc * 32 + ((lane >> 4) & 1) * 8 + (lane & 7));
    const uint32_t bc   = (uint32_t)((lane >> 3) & 1);

    // prefetch all 4 A chunks (one commit group each)
    #pragma unroll
    for (int h = 0; h < 4; h++) {
        #pragma unroll
        for (int it = 0; it < 4; it++) {
            int idx = t + it * 512;
            int r = idx >> 4, c = idx & 15;
            CP16(A0 + h * 32768 + sw2(r, c), asrc + (size_t)r * DIN + h * 128 + c * 8);
        }
        CP_COMMIT();
    }
    // prefetch B for iteration 0 (yc=0, h=0)
    {
        const __nv_bfloat16* bsrc = g_wqb;
        #pragma unroll
        for (int it = 0; it < 4; it++) {
            int idx = t + it * 512;
            int r = idx >> 4, c = idx & 15;
            CP16(SB[0] + sw2(r, c), bsrc + (size_t)r * DIN + c * 8);
        }
        CP_COMMIT();
    }

    float acc[8][4];

    for (int i = 0; i < 16; i++) {
        const int yc = i >> 2, h = i & 3, buf = i & 1;
        if (h == 0) {
            #pragma unroll
            for (int j = 0; j < 8; j++) { acc[j][0]=0.f; acc[j][1]=0.f; acc[j][2]=0.f; acc[j][3]=0.f; }
        }
        if (i + 1 < 16) {
            const int yn = (i + 1) >> 2, hn = (i + 1) & 3;
            const __nv_bfloat16* bsrc = ((yn < 2) ? g_wqb : g_wkb)
                                        + (size_t)((yn & 1) * 128) * DIN + hn * 128;
            #pragma unroll
            for (int it = 0; it < 4; it++) {
                int idx = t + it * 512;
                int r = idx >> 4, c = idx & 15;
                CP16(SB[1 - buf] + sw2(r, c), bsrc + (size_t)r * DIN + c * 8);
            }
            CP_COMMIT();
            CP_WAIT1();          // data for iteration i ready; prefetch i+1 in flight
        } else {
            CP_WAIT0();
        }
        __syncthreads();

        const uint32_t SAh = A0 + h * 32768;
        const uint32_t SBb = SB[buf];
        #pragma unroll
        for (int ks = 0; ks < 8; ks++) {
            uint32_t a0,a1,a2,a3,a4,a5,a6,a7;
            LDSM4(a0,a1,a2,a3, SAh + sw2(arow,      (uint32_t)(ks*2) + ac));
            LDSM4(a4,a5,a6,a7, SAh + sw2(arow + 16, (uint32_t)(ks*2) + ac));
            uint32_t b0,b1,b2,b3,b4,b5,b6,b7;
            LDSM4(b0,b1,b2,b3, SBb + sw2(brlo,      (uint32_t)(ks*2) + bc));
            LDSM4(b4,b5,b6,b7, SBb + sw2(brlo + 16, (uint32_t)(ks*2) + bc));
            mma16816(acc[0], a0,a1,a2,a3, b0,b1);
            mma16816(acc[1], a0,a1,a2,a3, b2,b3);
            mma16816(acc[2], a0,a1,a2,a3, b4,b5);
            mma16816(acc[3], a0,a1,a2,a3, b6,b7);
            mma16816(acc[4], a4,a5,a6,a7, b0,b1);
            mma16816(acc[5], a4,a5,a6,a7, b2,b3);
            mma16816(acc[6], a4,a5,a6,a7, b4,b5);
            mma16816(acc[7], a4,a5,a6,a7, b6,b7);
        }

        if (h == 3) {
            // epilogue for this yc: bias add, bf16 store
            const float* bias   = (yc < 2) ? bq : bk;
            __nv_bfloat16* outp = (yc < 2) ? g_qb : g_kb;
            const int col0 = (yc & 1) * 128;
            #pragma unroll
            for (int rb = 0; rb < 2; rb++) {
                #pragma unroll
                for (int nb = 0; nb < 4; nb++) {
                    const float* a4 = acc[rb * 4 + nb];
                    int col = col0 + wc * 32 + nb * 8 + (lane & 3) * 2;
                    float b0 = __ldg(bias + col), b1 = __ldg(bias + col + 1);
                    int ra = row0 + r0 + rb * 16 + (lane >> 2);
                    __nv_bfloat162 lo = __floats2bfloat162_rn(a4[0] + b0, a4[1] + b1);
                    __nv_bfloat162 hi = __floats2bfloat162_rn(a4[2] + b0, a4[3] + b1);
                    *(uint32_t*)(outp + (size_t)ra * DOUT + col)       = *(uint32_t*)&lo;
                    *(uint32_t*)(outp + (size_t)(ra + 8) * DOUT + col) = *(uint32_t*)&hi;
                }
            }
        }
        __syncthreads();   // all warps done reading SB[buf] before it is overwritten
    }
}

// ======================= fused attention: mma.sync scores, 4x4 warp grid =======================
// smem: Q 64KB | K0 64KB | K1 64KB | kvall 16KB | g3 2560B | red 4096B
#define AT_Q   0
#define AT_K0  65536
#define AT_K1  131072
#define AT_KV  196608
#define AT_G3  212992
#define AT_RED 215552
#define ATTN_SMEM (219648 + 1024)

__global__ __launch_bounds__(512, 1) void attn_mma(const long long* __restrict__ pr,
                                                   const float* __restrict__ bs_p,
                                                   float* __restrict__ out) {
    extern __shared__ char dsm[];
    uint32_t base0 = s2u(dsm);
    uint32_t A0 = (base0 + 1023u) & ~1023u;
    char* P = dsm + (A0 - base0);

    const int t = threadIdx.x, w = t >> 5, lane = t & 31;
    const int wr = w >> 2, wc = w & 3;
    const int b = blockIdx.y, n0 = blockIdx.x * 128;

    const uint32_t SQ = A0 + AT_Q;
    const uint32_t SK[2] = { A0 + AT_K0, A0 + AT_K1 };
    float2* kvall = (float2*)(P + AT_KV);
    float*  g3    = (float*)(P + AT_G3);
    float*  redl  = (float*)(P + AT_RED);        // [4][128]
    float*  reda  = (float*)(P + AT_RED + 2048); // [4][128]

    // initial async loads: Q tile + K tile 0
    const __nv_bfloat16* qsrc = g_qb + ((size_t)b * NN + n0) * DOUT;
    const __nv_bfloat16* ksrc = g_kb + (size_t)b * NN * DOUT;
    #pragma unroll
    for (int it = 0; it < 8; it++) {
        int idx = t + it * 512;
        int r = idx >> 5, c = idx & 31;
        CP16(SQ + sw(r, c), qsrc + (size_t)r * DOUT + c * 8);
        CP16(SK[0] + sw(r, c), ksrc + (size_t)r * DOUT + c * 8);
    }
    CP_COMMIT();

    // kvall + gate LUT
    #pragma unroll
    for (int it = 0; it < 4; it++) {
        int idx = t + it * 512;
        kvall[idx] = make_float2(g_s[(size_t)b * NN + idx],
                                 __int_as_float((int)pr[(size_t)b * NN + idx]));
    }
    for (int i = t; i < NBUCK * 32; i += 512) g3[i] = g_gate3[i >> 5];

    const int r0 = wr * 32;
    unsigned rn[4];
    #pragma unroll
    for (int i = 0; i < 4; i++)
        rn[i] = (unsigned)(int)pr[(size_t)b * NN + n0 + r0 + (lane >> 2) + i * 8];

    const uint32_t arow = (uint32_t)(r0 + ((lane >> 3) & 1) * 8 + (lane & 7));
    const uint32_t ac   = (uint32_t)((lane >> 4) & 1);
    const uint32_t brlo = (uint32_t)(wc * 32 + ((lane >> 4) & 1) * 8 + (lane & 7));
    const uint32_t bc   = (uint32_t)((lane >> 3) & 1);

    float lac[4], aac[4];
    #pragma unroll
    for (int i = 0; i < 4; i++) { lac[i] = 0.f; aac[i] = 0.f; }

    CP_WAIT0();
    __syncthreads();

    for (int tile = 0; tile < 16; tile++) {
        const int buf = tile & 1;
        if (tile + 1 < 16) {
            const __nv_bfloat16* kn = ksrc + (size_t)(tile + 1) * 128 * DOUT;
            #pragma unroll
            for (int it = 0; it < 8; it++) {
                int idx = t + it * 512;
                int r = idx >> 5, c = idx & 31;
                CP16(SK[1 - buf] + sw(r, c), kn + (size_t)r * DOUT + c * 8);
            }
            CP_COMMIT();
        }

        // ---- scores mma: warp covers rows r0..r0+31, cols wc*32..+31 ----
        float acc[8][4];
        #pragma unroll
        for (int j = 0; j < 8; j++) { acc[j][0]=0.f; acc[j][1]=0.f; acc[j][2]=0.f; acc[j][3]=0.f; }

        const uint32_t SKb = SK[buf];
        #pragma unroll
        for (int ks = 0; ks < 16; ks++) {
            uint32_t a0,a1,a2,a3,a4,a5,a6,a7;
            LDSM4(a0,a1,a2,a3, SQ + sw(arow,      (uint32_t)(ks*2) + ac));
            LDSM4(a4,a5,a6,a7, SQ + sw(arow + 16, (uint32_t)(ks*2) + ac));
            uint32_t b0,b1,b2,b3,b4,b5,b6,b7;
            LDSM4(b0,b1,b2,b3, SKb + sw(brlo,      (uint32_t)(ks*2) + bc));
            LDSM4(b4,b5,b6,b7, SKb + sw(brlo + 16, (uint32_t)(ks*2) + bc));
            mma16816(acc[0], a0,a1,a2,a3, b0,b1);
            mma16816(acc[1], a0,a1,a2,a3, b2,b3);
            mma16816(acc[2], a0,a1,a2,a3, b4,b5);
            mma16816(acc[3], a0,a1,a2,a3, b6,b7);
            mma16816(acc[4], a4,a5,a6,a7, b0,b1);
            mma16816(acc[5], a4,a5,a6,a7, b2,b3);
            mma16816(acc[6], a4,a5,a6,a7, b4,b5);
            mma16816(acc[7], a4,a5,a6,a7, b6,b7);
        }

        // ---- epilogue: nb outer so kv loads + rank converts are shared across rb ----
        const float2* kva = kvall + tile * 128;
        #pragma unroll
        for (int nb = 0; nb < 4; nb++) {
            int col = wc * 32 + nb * 8 + (lane & 3) * 2;
            float2 kv0 = kva[col];
            float2 kv1 = kva[col + 1];
            unsigned rm0 = (unsigned)__float_as_int(kv0.y);
            unsigned rm1 = (unsigned)__float_as_int(kv1.y);
            #pragma unroll
            for (int rb = 0; rb < 2; rb++) {
                const float* a4 = acc[rb * 4 + nb];
                unsigned rA = rn[rb * 2], rB = rn[rb * 2 + 1];
                unsigned k00 = __usad(rA, rm0, 0u) / 5u; k00 = umin(k00, NBUCK - 1u);
                unsigned k01 = __usad(rA, rm1, 0u) / 5u; k01 = umin(k01, NBUCK - 1u);
                unsigned k10 = __usad(rB, rm0, 0u) / 5u; k10 = umin(k10, NBUCK - 1u);
                unsigned k11 = __usad(rB, rm1, 0u) / 5u; k11 = umin(k11, NBUCK - 1u);
                float e;
                e = exp2_fast(a4[0] * g3[k00 * 32 + lane]); lac[rb*2]   += e; aac[rb*2]   = fmaf(e, kv0.x, aac[rb*2]);
                e = exp2_fast(a4[1] * g3[k01 * 32 + lane]); lac[rb*2]   += e; aac[rb*2]   = fmaf(e, kv1.x, aac[rb*2]);
                e = exp2_fast(a4[2] * g3[k10 * 32 + lane]); lac[rb*2+1] += e; aac[rb*2+1] = fmaf(e, kv0.x, aac[rb*2+1]);
                e = exp2_fast(a4[3] * g3[k11 * 32 + lane]); lac[rb*2+1] += e; aac[rb*2+1] = fmaf(e, kv1.x, aac[rb*2+1]);
            }
        }

        CP_WAIT0();
        __syncthreads();
    }

    // intra-warp reduce over the 4 lanes sharing each row
    #pragma unroll
    for (int s = 1; s <= 2; s <<= 1) {
        #pragma unroll
        for (int i = 0; i < 4; i++) {
            lac[i] += __shfl_xor_sync(0xffffffffu, lac[i], s);
            aac[i] += __shfl_xor_sync(0xffffffffu, aac[i], s);
        }
    }
    if ((lane & 3) == 0) {
        #pragma unroll
        for (int i = 0; i < 4; i++) {
            int row = r0 + (lane >> 2) + i * 8;
            redl[wc * 128 + row] = lac[i];
            reda[wc * 128 + row] = aac[i];
        }
    }
    __syncthreads();
    if (t < 128) {
        float L = redl[t] + redl[128 + t] + redl[256 + t] + redl[384 + t];
        float A = reda[t] + reda[128 + t] + reda[256 + t] + reda[384 + t];
        float z = A / L + bs_p[0];
        out[(size_t)b * NN + n0 + t] = 1.f / (1.f + expf(-z));
    }
}

// ======================= launcher =======================
extern "C" void kernel_launch(void* const* d_in, const int* in_sizes, int n_in,
                              void* d_out, int out_size) {
    const float*     x    = (const float*)d_in[0];
    const long long* pr   = (const long long*)d_in[1];
    const float*     Wq   = (const float*)d_in[2];
    const float*     bq   = (const float*)d_in[3];
    const float*     Wk   = (const float*)d_in[4];
    const float*     bk   = (const float*)d_in[5];
    const float*     Wv   = (const float*)d_in[6];
    const float*     bv   = (const float*)d_in[7];
    const float*     Ws   = (const float*)d_in[8];
    const float*     bs   = (const float*)d_in[9];
    const float*     remb = (const float*)d_in[10];
    const float*     rw   = (const float*)d_in[11];
    float* out = (float*)d_out;

    prep_all<<<9, 64>>>(Wv, bv, Ws, remb, rw);        // wvs + gate + bvs
    wconv<<<256, 256>>>(Wq, Wk);                      // weights -> bf16
    xs_kernel<<<ROWS/8, 256>>>(x);                    // x -> bf16 fused with s

    cudaFuncSetAttribute(qk_mma, cudaFuncAttributeMaxDynamicSharedMemorySize, QKP_SMEM);
    qk_mma<<<ROWS/128, 512, QKP_SMEM>>>(bq, bk);

    cudaFuncSetAttribute(attn_mma, cudaFuncAttributeMaxDynamicSharedMemorySize, ATTN_SMEM);
    dim3 g2(NN/128, BB);
    attn_mma<<<g2, 512, ATTN_SMEM>>>(pr, bs, out);
}